// round 8
// baseline (speedup 1.0000x reference)
#include <cuda_runtime.h>
#include <cuda_bf16.h>
#include <cstdint>

// ============================================================================
// Attention_84129819394524 — bf16-split mma.sync (R4 GEMM config) +
// fused softmax dataflow:
//   s_mma  : logits -> attn buffer + per-segment (max, sumexp) partials
//   combine: per-row (max, 1/sum)
//   o_mma  : reads logits, normalizes on the fly, writes normalized attn
//            back in place, and computes O = P @ V via bf16-split MMA.
// ============================================================================

#define NUM_HEADS 12
#define HEAD_DIM  64
#define DIMC      768
#define BATCH     4
#define SEQ       1024
#define SCALE_F   0.125f

#define M_TOK   (BATCH * SEQ)          // 4096
#define QKV_N   (3 * DIMC)             // 2304
#define BH      (BATCH * NUM_HEADS)    // 48

#define OUT_ELEMS  ((size_t)M_TOK * DIMC)
#define ATTN_ELEMS ((size_t)BH * SEQ * SEQ)

// ---------------- device scratch (allocation-free) ----------------
__device__ __align__(16) __nv_bfloat16 g_xh [M_TOK * DIMC];
__device__ __align__(16) __nv_bfloat16 g_xl [M_TOK * DIMC];
__device__ __align__(16) __nv_bfloat16 g_wqh[QKV_N * DIMC];
__device__ __align__(16) __nv_bfloat16 g_wql[QKV_N * DIMC];
__device__ __align__(16) __nv_bfloat16 g_wph[DIMC * DIMC];
__device__ __align__(16) __nv_bfloat16 g_wpl[DIMC * DIMC];
__device__ __align__(16) __nv_bfloat16 g_qh [BH * SEQ * HEAD_DIM];
__device__ __align__(16) __nv_bfloat16 g_ql [BH * SEQ * HEAD_DIM];
__device__ __align__(16) __nv_bfloat16 g_kh [BH * SEQ * HEAD_DIM];
__device__ __align__(16) __nv_bfloat16 g_kl [BH * SEQ * HEAD_DIM];
__device__ __align__(16) __nv_bfloat16 g_vh [BH * SEQ * HEAD_DIM];
__device__ __align__(16) __nv_bfloat16 g_vl [BH * SEQ * HEAD_DIM];
__device__ __align__(16) __nv_bfloat16 g_vth[BH * HEAD_DIM * SEQ];
__device__ __align__(16) __nv_bfloat16 g_vtl[BH * HEAD_DIM * SEQ];
__device__ __align__(16) __nv_bfloat16 g_oh [M_TOK * DIMC];
__device__ __align__(16) __nv_bfloat16 g_ol [M_TOK * DIMC];
__device__ __align__(16) float g_smax[BH * SEQ * 16];
__device__ __align__(16) float g_ssum[BH * SEQ * 16];
__device__ __align__(16) float g_rowm[BH * SEQ];
__device__ __align__(16) float g_rowi[BH * SEQ];
__device__ __align__(256) float g_attn[ATTN_ELEMS];
__device__ __align__(256) float g_outs[OUT_ELEMS];

// ---------------- helpers ----------------
__device__ __forceinline__ uint32_t smem_u32(const void* p) {
    return (uint32_t)__cvta_generic_to_shared(p);
}
__device__ __forceinline__ void cpasync16(uint32_t dst, const void* src) {
    asm volatile("cp.async.cg.shared.global [%0], [%1], 16;" :: "r"(dst), "l"(src));
}
__device__ __forceinline__ void ldsm_x4(uint32_t* r, uint32_t addr) {
    asm volatile("ldmatrix.sync.aligned.m8n8.x4.shared.b16 {%0,%1,%2,%3}, [%4];"
                 : "=r"(r[0]), "=r"(r[1]), "=r"(r[2]), "=r"(r[3]) : "r"(addr));
}
__device__ __forceinline__ void mma16816(float* c, const uint32_t* a, const uint32_t* b) {
    asm volatile("mma.sync.aligned.m16n8k16.row.col.f32.bf16.bf16.f32 "
                 "{%0,%1,%2,%3}, {%4,%5,%6,%7}, {%8,%9}, {%0,%1,%2,%3};"
                 : "+f"(c[0]), "+f"(c[1]), "+f"(c[2]), "+f"(c[3])
                 : "r"(a[0]), "r"(a[1]), "r"(a[2]), "r"(a[3]), "r"(b[0]), "r"(b[1]));
}
__device__ __forceinline__ void split2(float v, __nv_bfloat16& h, __nv_bfloat16& l) {
    h = __float2bfloat16_rn(v);
    l = __float2bfloat16_rn(v - __bfloat162float(h));
}
__device__ __forceinline__ uint32_t pack_bf2(__nv_bfloat16 a, __nv_bfloat16 b) {
    __nv_bfloat162 t(a, b);
    return *(uint32_t*)&t;
}

// ============================================================================
// R4 mainloop: block 128 x BN of C = A @ B^T, 256 threads, warps 4(m) x 2(n),
// warp tile 32x64.  k32 chunks, 2-stage cp.async double buffer, SPAD=40.
// ============================================================================
#define SPAD 40

template<int BN>
__device__ __forceinline__ void gemm_tile(
    const __nv_bfloat16* __restrict__ Agh, const __nv_bfloat16* __restrict__ Agl, int lda,
    const __nv_bfloat16* __restrict__ Bgh, const __nv_bfloat16* __restrict__ Bgl, int ldb,
    int K, float (&acc)[2][BN / 16][4])
{
    extern __shared__ char smem_raw[];
    constexpr int NT   = BN / 16;
    constexpr int ASZ  = 128 * SPAD * 2;
    constexpr int BSZ  = BN  * SPAD * 2;
    constexpr int STAGE = 2 * ASZ + 2 * BSZ;

    const int tid  = threadIdx.x;
    const int lane = tid & 31;
    const int warp = tid >> 5;
    const int wm = (warp >> 1) * 32;
    const int wn = (warp & 1) * (BN / 2);

    const int lc = tid & 3;
    const int lr = tid >> 2;

    const uint32_t sbase = smem_u32(smem_raw);

    auto load_stage = [&](int s, int k0) {
        uint32_t base = sbase + s * STAGE;
#pragma unroll
        for (int rr = 0; rr < 2; rr++) {
            int row = lr + rr * 64;
            uint32_t doff = (uint32_t)(row * SPAD + lc * 8) * 2;
            cpasync16(base + doff,       Agh + (size_t)row * lda + k0 + lc * 8);
            cpasync16(base + ASZ + doff, Agl + (size_t)row * lda + k0 + lc * 8);
        }
#pragma unroll
        for (int rr = 0; rr < BN / 64; rr++) {
            int row = lr + rr * 64;
            uint32_t doff = (uint32_t)(row * SPAD + lc * 8) * 2;
            cpasync16(base + 2 * ASZ + doff,       Bgh + (size_t)row * ldb + k0 + lc * 8);
            cpasync16(base + 2 * ASZ + BSZ + doff, Bgl + (size_t)row * ldb + k0 + lc * 8);
        }
    };

    const int a_row = wm + (lane & 15);
    const int a_co  = (lane >> 4) << 3;
    const int g     = lane >> 3;
    const int b_rowbase = wn + (g >> 1) * 8 + (lane & 7);
    const int b_co  = (g & 1) * 8;

    int niter = K >> 5;
    load_stage(0, 0);
    asm volatile("cp.async.commit_group;");

    for (int it = 0; it < niter; it++) {
        int buf = it & 1;
        if (it + 1 < niter) {
            load_stage(buf ^ 1, (it + 1) * 32);
            asm volatile("cp.async.commit_group;");
            asm volatile("cp.async.wait_group 1;");
        } else {
            asm volatile("cp.async.wait_group 0;");
        }
        __syncthreads();

        uint32_t sb = sbase + buf * STAGE;
#pragma unroll
        for (int k16 = 0; k16 < 32; k16 += 16) {
            uint32_t ah[2][4], al[2][4];
#pragma unroll
            for (int mt = 0; mt < 2; mt++) {
                uint32_t addr = sb + (uint32_t)(((a_row + mt * 16) * SPAD + k16 + a_co) * 2);
                ldsm_x4(ah[mt], addr);
                ldsm_x4(al[mt], addr + ASZ);
            }
            uint32_t bhf[NT][2], blf[NT][2];
#pragma unroll
            for (int u = 0; u < NT; u += 2) {
                uint32_t addr = sb + 2 * ASZ +
                    (uint32_t)(((b_rowbase + u * 8) * SPAD + k16 + b_co) * 2);
                uint32_t t[4];
                ldsm_x4(t, addr);
                bhf[u][0] = t[0]; bhf[u][1] = t[1];
                bhf[u + 1][0] = t[2]; bhf[u + 1][1] = t[3];
                ldsm_x4(t, addr + BSZ);
                blf[u][0] = t[0]; blf[u][1] = t[1];
                blf[u + 1][0] = t[2]; blf[u + 1][1] = t[3];
            }
#pragma unroll
            for (int mt = 0; mt < 2; mt++) {
#pragma unroll
                for (int u = 0; u < NT; u++) {
                    mma16816(acc[mt][u], ah[mt], bhf[u]);
                    mma16816(acc[mt][u], ah[mt], blf[u]);
                    mma16816(acc[mt][u], al[mt], bhf[u]);
                }
            }
        }
        __syncthreads();
    }
}

// ============================================================================
// split: fp32 -> (hi, lo) bf16
// ============================================================================
__global__ __launch_bounds__(256)
void split_kernel(const float4* __restrict__ src, __nv_bfloat162* __restrict__ hi,
                  __nv_bfloat162* __restrict__ lo, int n4)
{
    int i = blockIdx.x * blockDim.x + threadIdx.x;
    if (i >= n4) return;
    float4 v = src[i];
    __nv_bfloat16 h0, h1, h2, h3, l0, l1, l2, l3;
    split2(v.x, h0, l0); split2(v.y, h1, l1);
    split2(v.z, h2, l2); split2(v.w, h3, l3);
    hi[2 * i]     = __nv_bfloat162(h0, h1);
    hi[2 * i + 1] = __nv_bfloat162(h2, h3);
    lo[2 * i]     = __nv_bfloat162(l0, l1);
    lo[2 * i + 1] = __nv_bfloat162(l2, l3);
}

// ============================================================================
// K1: QKV GEMM [4096 x 2304] (R4 config).  Epilogue scatters q/k/v hi/lo.
// ============================================================================
__global__ __launch_bounds__(256)
void qkv_mma()
{
    float acc[2][8][4];
#pragma unroll
    for (int a = 0; a < 2; a++)
#pragma unroll
        for (int b = 0; b < 8; b++)
#pragma unroll
            for (int c = 0; c < 4; c++) acc[a][b][c] = 0.f;

    const int bx = blockIdx.x, by = blockIdx.y;
    gemm_tile<128>(g_xh + (size_t)(by * 128) * DIMC, g_xl + (size_t)(by * 128) * DIMC, DIMC,
                   g_wqh + (size_t)(bx * 128) * DIMC, g_wql + (size_t)(bx * 128) * DIMC, DIMC,
                   DIMC, acc);

    const int lane = threadIdx.x & 31, warp = threadIdx.x >> 5;
    const int wm = (warp >> 1) * 32, wn = (warp & 1) * 64;
    const int r = lane >> 2, cc = (lane & 3) * 2;

    const int which = bx / 6;
    __nv_bfloat16 *dh, *dl;
    float scl = 1.f;
    if (which == 0)      { dh = g_qh; dl = g_ql; scl = SCALE_F; }
    else if (which == 1) { dh = g_kh; dl = g_kl; }
    else                 { dh = g_vh; dl = g_vl; }
    const int cbase = bx * 128 - which * DIMC;

#pragma unroll
    for (int mt = 0; mt < 2; mt++) {
#pragma unroll
        for (int nt = 0; nt < 8; nt++) {
            int c = cbase + wn + nt * 8 + cc;
            int h = c >> 6, d = c & 63;
#pragma unroll
            for (int half = 0; half < 2; half++) {
                int m = by * 128 + wm + mt * 16 + r + half * 8;
                int b = m >> 10, qi = m & 1023;
                size_t idx = (((size_t)(b * NUM_HEADS + h) * SEQ) + qi) * HEAD_DIM + d;
                float v0 = acc[mt][nt][half * 2]     * scl;
                float v1 = acc[mt][nt][half * 2 + 1] * scl;
                __nv_bfloat16 h0, h1, l0, l1;
                split2(v0, h0, l0); split2(v1, h1, l1);
                *(__nv_bfloat162*)&dh[idx] = __nv_bfloat162(h0, h1);
                *(__nv_bfloat162*)&dl[idx] = __nv_bfloat162(l0, l1);
            }
        }
    }
}

// ============================================================================
// K2: transpose v -> vt (hi, lo)
// ============================================================================
__global__ __launch_bounds__(256)
void vt_kernel()
{
    __shared__ __nv_bfloat16 tile[32][33];
    const int bh = blockIdx.z, bx = blockIdx.x, by = blockIdx.y;
    const int tx = threadIdx.x, ty = threadIdx.y;
#pragma unroll
    for (int which = 0; which < 2; which++) {
        const __nv_bfloat16* src = (which ? g_vl : g_vh) + (size_t)bh * SEQ * HEAD_DIM;
        __nv_bfloat16* dst = (which ? g_vtl : g_vth) + (size_t)bh * HEAD_DIM * SEQ;
#pragma unroll
        for (int j = 0; j < 4; j++) {
            int s = bx * 32 + ty + j * 8;
            tile[ty + j * 8][tx] = src[(size_t)s * HEAD_DIM + by * 32 + tx];
        }
        __syncthreads();
#pragma unroll
        for (int j = 0; j < 4; j++) {
            int d = by * 32 + ty + j * 8;
            dst[(size_t)d * SEQ + bx * 32 + tx] = tile[tx][ty + j * 8];
        }
        __syncthreads();
    }
}

// ============================================================================
// K3: S = q @ k^T per (b,h) (R4 config) + per-segment softmax partials.
// ============================================================================
__global__ __launch_bounds__(256)
void s_mma(float* attn_out)
{
    float* attn = attn_out ? attn_out : g_attn;
    float acc[2][8][4];
#pragma unroll
    for (int a = 0; a < 2; a++)
#pragma unroll
        for (int b = 0; b < 8; b++)
#pragma unroll
            for (int c = 0; c < 4; c++) acc[a][b][c] = 0.f;

    const int bh = blockIdx.z, bx = blockIdx.x, by = blockIdx.y;
    const size_t hb = (size_t)bh * SEQ * HEAD_DIM;
    gemm_tile<128>(g_qh + hb + (size_t)(by * 128) * HEAD_DIM,
                   g_ql + hb + (size_t)(by * 128) * HEAD_DIM, HEAD_DIM,
                   g_kh + hb + (size_t)(bx * 128) * HEAD_DIM,
                   g_kl + hb + (size_t)(bx * 128) * HEAD_DIM, HEAD_DIM,
                   HEAD_DIM, acc);

    const int lane = threadIdx.x & 31, warp = threadIdx.x >> 5;
    const int wm = (warp >> 1) * 32, wn = (warp & 1) * 64;
    const int r = lane >> 2, cc = (lane & 3) * 2;
    float* C = attn + (size_t)bh * SEQ * SEQ;

#pragma unroll
    for (int mt = 0; mt < 2; mt++) {
#pragma unroll
        for (int nt = 0; nt < 8; nt++) {
            int n = bx * 128 + wn + nt * 8 + cc;
#pragma unroll
            for (int half = 0; half < 2; half++) {
                int m = by * 128 + wm + mt * 16 + r + half * 8;
                *(float2*)&C[(size_t)m * SEQ + n] =
                    make_float2(acc[mt][nt][half * 2], acc[mt][nt][half * 2 + 1]);
            }
        }
    }

    // partial softmax stats: per (row, 64-col warp segment): max, sum(exp(v-max))
    const int sx = bx * 2 + (warp & 1);         // segment index 0..15
#pragma unroll
    for (int mt = 0; mt < 2; mt++) {
#pragma unroll
        for (int half = 0; half < 2; half++) {
            float mx = -1e30f;
#pragma unroll
            for (int nt = 0; nt < 8; nt++) {
                mx = fmaxf(mx, fmaxf(acc[mt][nt][half * 2], acc[mt][nt][half * 2 + 1]));
            }
            mx = fmaxf(mx, __shfl_xor_sync(0xFFFFFFFFu, mx, 1));
            mx = fmaxf(mx, __shfl_xor_sync(0xFFFFFFFFu, mx, 2));
            float sm = 0.f;
#pragma unroll
            for (int nt = 0; nt < 8; nt++) {
                sm += __expf(acc[mt][nt][half * 2]     - mx);
                sm += __expf(acc[mt][nt][half * 2 + 1] - mx);
            }
            sm += __shfl_xor_sync(0xFFFFFFFFu, sm, 1);
            sm += __shfl_xor_sync(0xFFFFFFFFu, sm, 2);
            if ((lane & 3) == 0) {
                int m = by * 128 + wm + mt * 16 + r + half * 8;
                size_t si = ((size_t)bh * SEQ + m) * 16 + sx;
                g_smax[si] = mx;
                g_ssum[si] = sm;
            }
        }
    }
}

// ============================================================================
// K4: combine partials -> per-row (max, 1/sum)
// ============================================================================
__global__ __launch_bounds__(256)
void combine_kernel()
{
    int row = blockIdx.x * 256 + threadIdx.x;   // < BH*SEQ
    const float* pm = g_smax + (size_t)row * 16;
    const float* ps = g_ssum + (size_t)row * 16;
    float m = -1e30f;
#pragma unroll
    for (int i = 0; i < 16; i++) m = fmaxf(m, pm[i]);
    float s = 0.f;
#pragma unroll
    for (int i = 0; i < 16; i++) s += ps[i] * __expf(pm[i] - m);
    g_rowm[row] = m;
    g_rowi[row] = 1.0f / s;
}

// ============================================================================
// K5: O = P @ vt^T per (b,h).  BM=256, BN=64, 8 warps (32x64), K=1024.
// A = fp32 logits: LDG -> normalize (exp(s-m)*inv) -> write back to attn
// -> split hi/lo -> STS.  B = vt hi/lo via cp.async.
// ============================================================================
__global__ __launch_bounds__(256)
void o_mma(float* attn_io)
{
    float* attn = attn_io ? attn_io : g_attn;
    constexpr int BM = 256, BN = 64;
    constexpr int APL = BM * SPAD * 2;       // 20480
    constexpr int BPL = BN * SPAD * 2;       // 5120
    constexpr int STAGE = 2 * APL + 2 * BPL; // 51200
    extern __shared__ char smem_raw[];

    const int tid = threadIdx.x, lane = tid & 31, warp = tid >> 5;
    const int bh = blockIdx.y, bx = blockIdx.x;
    const int b = bh / NUM_HEADS, h = bh - b * NUM_HEADS;
    float* Pg = attn + (size_t)bh * SEQ * SEQ + (size_t)(bx * 256) * SEQ;
    const __nv_bfloat16* Bgh = g_vth + (size_t)bh * HEAD_DIM * SEQ;
    const __nv_bfloat16* Bgl = g_vtl + (size_t)bh * HEAD_DIM * SEQ;
    const uint32_t sb0 = smem_u32(smem_raw);

    float acc[2][8][4];
#pragma unroll
    for (int a = 0; a < 2; a++)
#pragma unroll
        for (int bb = 0; bb < 8; bb++)
#pragma unroll
            for (int c = 0; c < 4; c++) acc[a][bb][c] = 0.f;

    // per-thread fixed rows: p = tid + u*256 -> row = p>>2 (each row 4 threads)
    float m_u[4], i_u[4];
#pragma unroll
    for (int u = 0; u < 4; u++) {
        int row = (tid + u * 256) >> 2;
        size_t ri = (size_t)bh * SEQ + bx * 256 + row;
        m_u[u] = g_rowm[ri];
        i_u[u] = g_rowi[ri];
    }

    uint4 hr[4], lr_[4];
    auto ldgA = [&](int k0) {
#pragma unroll
        for (int u = 0; u < 4; u++) {
            int p = tid + u * 256;
            int row = p >> 2, ch = p & 3;
            float* s = Pg + (size_t)row * SEQ + k0 + ch * 8;
            float4 a = *(const float4*)s;
            float4 c = *(const float4*)(s + 4);
            const float mm = m_u[u], ii = i_u[u];
            a.x = __expf(a.x - mm) * ii; a.y = __expf(a.y - mm) * ii;
            a.z = __expf(a.z - mm) * ii; a.w = __expf(a.w - mm) * ii;
            c.x = __expf(c.x - mm) * ii; c.y = __expf(c.y - mm) * ii;
            c.z = __expf(c.z - mm) * ii; c.w = __expf(c.w - mm) * ii;
            *(float4*)s       = a;       // normalized attn back to d_out
            *(float4*)(s + 4) = c;
            __nv_bfloat16 h0,h1,h2,h3,h4,h5,h6,h7, l0,l1,l2,l3,l4,l5,l6,l7;
            split2(a.x,h0,l0); split2(a.y,h1,l1); split2(a.z,h2,l2); split2(a.w,h3,l3);
            split2(c.x,h4,l4); split2(c.y,h5,l5); split2(c.z,h6,l6); split2(c.w,h7,l7);
            hr[u]  = make_uint4(pack_bf2(h0,h1), pack_bf2(h2,h3),
                                pack_bf2(h4,h5), pack_bf2(h6,h7));
            lr_[u] = make_uint4(pack_bf2(l0,l1), pack_bf2(l2,l3),
                                pack_bf2(l4,l5), pack_bf2(l6,l7));
        }
    };
    auto stsA = [&](int buf) {
        char* base = smem_raw + buf * STAGE;
#pragma unroll
        for (int u = 0; u < 4; u++) {
            int p = tid + u * 256;
            int row = p >> 2, ch = p & 3;
            uint32_t off = (uint32_t)(row * SPAD + ch * 8) * 2;
            *(uint4*)(base + off)       = hr[u];
            *(uint4*)(base + APL + off) = lr_[u];
        }
    };
    auto fillB = [&](int buf, int k0) {
        int row = tid >> 2, ch = tid & 3;
        uint32_t off = (uint32_t)(row * SPAD + ch * 8) * 2;
        uint32_t base = sb0 + (uint32_t)buf * STAGE;
        cpasync16(base + 2 * APL + off,       Bgh + (size_t)row * SEQ + k0 + ch * 8);
        cpasync16(base + 2 * APL + BPL + off, Bgl + (size_t)row * SEQ + k0 + ch * 8);
        asm volatile("cp.async.commit_group;");
    };

    const int a_row = warp * 32 + (lane & 15);
    const int a_co  = (lane >> 4) << 3;
    const int g     = lane >> 3;
    const int b_rowbase = (g >> 1) * 8 + (lane & 7);
    const int b_co  = (g & 1) * 8;

    const int niter = SEQ >> 5;     // 32
    ldgA(0); stsA(0);
    fillB(0, 0);
    for (int it = 0; it < niter; it++) {
        if (it + 1 < niter) {
            ldgA((it + 1) * 32);
            fillB((it + 1) & 1, (it + 1) * 32);
            asm volatile("cp.async.wait_group 1;");
        } else {
            asm volatile("cp.async.wait_group 0;");
        }
        __syncthreads();
        const uint32_t sb = sb0 + (uint32_t)(it & 1) * STAGE;
#pragma unroll
        for (int k16 = 0; k16 < 32; k16 += 16) {
            uint32_t ah[2][4], al[2][4];
#pragma unroll
            for (int mt = 0; mt < 2; mt++) {
                uint32_t addr = sb + (uint32_t)(((a_row + mt * 16) * SPAD + k16 + a_co) * 2);
                ldsm_x4(ah[mt], addr);
                ldsm_x4(al[mt], addr + APL);
            }
            uint32_t bhf[8][2], blf[8][2];
#pragma unroll
            for (int u = 0; u < 8; u += 2) {
                uint32_t addr = sb + 2 * APL +
                    (uint32_t)(((b_rowbase + u * 8) * SPAD + k16 + b_co) * 2);
                uint32_t t[4];
                ldsm_x4(t, addr);
                bhf[u][0] = t[0]; bhf[u][1] = t[1];
                bhf[u + 1][0] = t[2]; bhf[u + 1][1] = t[3];
                ldsm_x4(t, addr + BPL);
                blf[u][0] = t[0]; blf[u][1] = t[1];
                blf[u + 1][0] = t[2]; blf[u + 1][1] = t[3];
            }
#pragma unroll
            for (int mt = 0; mt < 2; mt++) {
#pragma unroll
                for (int u = 0; u < 8; u++) {
                    mma16816(acc[mt][u], ah[mt], bhf[u]);
                    mma16816(acc[mt][u], ah[mt], blf[u]);
                    mma16816(acc[mt][u], al[mt], bhf[u]);
                }
            }
        }
        if (it + 1 < niter) stsA((it + 1) & 1);
        __syncthreads();
    }

    const int r = lane >> 2, cc = (lane & 3) * 2;
#pragma unroll
    for (int mt = 0; mt < 2; mt++) {
#pragma unroll
        for (int nt = 0; nt < 8; nt++) {
            int d = nt * 8 + cc;
#pragma unroll
            for (int half = 0; half < 2; half++) {
                int mseq = bx * 256 + warp * 32 + mt * 16 + r + half * 8;
                size_t idx = ((size_t)b * SEQ + mseq) * DIMC + h * HEAD_DIM + d;
                float v0 = acc[mt][nt][half * 2];
                float v1 = acc[mt][nt][half * 2 + 1];
                __nv_bfloat16 h0, h1, l0, l1;
                split2(v0, h0, l0); split2(v1, h1, l1);
                *(__nv_bfloat162*)&g_oh[idx] = __nv_bfloat162(h0, h1);
                *(__nv_bfloat162*)&g_ol[idx] = __nv_bfloat162(l0, l1);
            }
        }
    }
}

// ============================================================================
// K6: out = O @ w_proj^T + bias (R4 config).
// ============================================================================
__global__ __launch_bounds__(256)
void proj_mma(const float* __restrict__ bias, float* out_ptr)
{
    float* outp = out_ptr ? out_ptr : g_outs;
    float acc[2][8][4];
#pragma unroll
    for (int a = 0; a < 2; a++)
#pragma unroll
        for (int b = 0; b < 8; b++)
#pragma unroll
            for (int c = 0; c < 4; c++) acc[a][b][c] = 0.f;

    const int bx = blockIdx.x, by = blockIdx.y;
    gemm_tile<128>(g_oh + (size_t)(by * 128) * DIMC, g_ol + (size_t)(by * 128) * DIMC, DIMC,
                   g_wph + (size_t)(bx * 128) * DIMC, g_wpl + (size_t)(bx * 128) * DIMC, DIMC,
                   DIMC, acc);

    const int lane = threadIdx.x & 31, warp = threadIdx.x >> 5;
    const int wm = (warp >> 1) * 32, wn = (warp & 1) * 64;
    const int r = lane >> 2, cc = (lane & 3) * 2;

#pragma unroll
    for (int mt = 0; mt < 2; mt++) {
#pragma unroll
        for (int nt = 0; nt < 8; nt++) {
            int n = bx * 128 + wn + nt * 8 + cc;
            float b0 = bias[n], b1 = bias[n + 1];
#pragma unroll
            for (int half = 0; half < 2; half++) {
                int m = by * 128 + wm + mt * 16 + r + half * 8;
                *(float2*)&outp[(size_t)m * DIMC + n] =
                    make_float2(acc[mt][nt][half * 2] + b0, acc[mt][nt][half * 2 + 1] + b1);
            }
        }
    }
}

// ============================================================================
// launch
// ============================================================================
extern "C" void kernel_launch(void* const* d_in, const int* in_sizes, int n_in,
                              void* d_out, int out_size)
{
    const float* x      = (const float*)d_in[0];
    const float* w_qkv  = (const float*)d_in[1];
    const float* w_proj = (const float*)d_in[2];
    const float* b_proj = (const float*)d_in[3];
    (void)in_sizes; (void)n_in;

    float* dof = (float*)d_out;
    float* out_ptr  = nullptr;
    float* attn_ptr = nullptr;
    size_t osz = (size_t)out_size;
    if (osz >= OUT_ELEMS + ATTN_ELEMS) { out_ptr = dof; attn_ptr = dof + OUT_ELEMS; }
    else if (osz == ATTN_ELEMS)        { attn_ptr = dof; }
    else                               { out_ptr = dof; }

    const int SM_BIG = 2 * (2 * 128 * SPAD * 2 + 2 * 128 * SPAD * 2);  // 81920
    const int SM_O   = 2 * (2 * 256 * SPAD * 2 + 2 * 64  * SPAD * 2);  // 102400
    cudaFuncSetAttribute(qkv_mma,  cudaFuncAttributeMaxDynamicSharedMemorySize, SM_BIG);
    cudaFuncSetAttribute(s_mma,    cudaFuncAttributeMaxDynamicSharedMemorySize, SM_BIG);
    cudaFuncSetAttribute(proj_mma, cudaFuncAttributeMaxDynamicSharedMemorySize, SM_BIG);
    cudaFuncSetAttribute(o_mma,    cudaFuncAttributeMaxDynamicSharedMemorySize, SM_O);

    void *p_xh, *p_xl, *p_wqh, *p_wql, *p_wph, *p_wpl;
    cudaGetSymbolAddress(&p_xh, g_xh);   cudaGetSymbolAddress(&p_xl, g_xl);
    cudaGetSymbolAddress(&p_wqh, g_wqh); cudaGetSymbolAddress(&p_wql, g_wql);
    cudaGetSymbolAddress(&p_wph, g_wph); cudaGetSymbolAddress(&p_wpl, g_wpl);

    dim3 blk(256);

    { int n4 = M_TOK * DIMC / 4;
      split_kernel<<<(n4 + 255) / 256, blk>>>((const float4*)x,
          (__nv_bfloat162*)p_xh, (__nv_bfloat162*)p_xl, n4); }
    { int n4 = QKV_N * DIMC / 4;
      split_kernel<<<(n4 + 255) / 256, blk>>>((const float4*)w_qkv,
          (__nv_bfloat162*)p_wqh, (__nv_bfloat162*)p_wql, n4); }
    { int n4 = DIMC * DIMC / 4;
      split_kernel<<<(n4 + 255) / 256, blk>>>((const float4*)w_proj,
          (__nv_bfloat162*)p_wph, (__nv_bfloat162*)p_wpl, n4); }

    qkv_mma<<<dim3(QKV_N / 128, M_TOK / 128), blk, SM_BIG>>>();

    vt_kernel<<<dim3(SEQ / 32, HEAD_DIM / 32, BH), dim3(32, 8)>>>();

    s_mma<<<dim3(SEQ / 128, SEQ / 128, BH), blk, SM_BIG>>>(attn_ptr);

    combine_kernel<<<dim3(BH * SEQ / 256), blk>>>();

    o_mma<<<dim3(SEQ / 256, BH), blk, SM_O>>>(attn_ptr);

    proj_mma<<<dim3(DIMC / 128, M_TOK / 128), blk, SM_BIG>>>(b_proj, out_ptr);
}

// round 9
// speedup vs baseline: 1.2459x; 1.2459x over previous
#include <cuda_runtime.h>
#include <cuda_bf16.h>
#include <cstdint>

// ============================================================================
// Attention_84129819394524 — bf16-split mma.sync (R4 GEMM config).
// Delta vs R4: softmax no longer emits bf16 P planes; o_mma reads the
// normalized fp32 attn directly (LDG -> split -> STS), saving 201 MB.
// ============================================================================

#define NUM_HEADS 12
#define HEAD_DIM  64
#define DIMC      768
#define BATCH     4
#define SEQ       1024
#define SCALE_F   0.125f

#define M_TOK   (BATCH * SEQ)          // 4096
#define QKV_N   (3 * DIMC)             // 2304
#define BH      (BATCH * NUM_HEADS)    // 48

#define OUT_ELEMS  ((size_t)M_TOK * DIMC)
#define ATTN_ELEMS ((size_t)BH * SEQ * SEQ)

// ---------------- device scratch (allocation-free) ----------------
__device__ __align__(16) __nv_bfloat16 g_xh [M_TOK * DIMC];
__device__ __align__(16) __nv_bfloat16 g_xl [M_TOK * DIMC];
__device__ __align__(16) __nv_bfloat16 g_wqh[QKV_N * DIMC];
__device__ __align__(16) __nv_bfloat16 g_wql[QKV_N * DIMC];
__device__ __align__(16) __nv_bfloat16 g_wph[DIMC * DIMC];
__device__ __align__(16) __nv_bfloat16 g_wpl[DIMC * DIMC];
__device__ __align__(16) __nv_bfloat16 g_qh [BH * SEQ * HEAD_DIM];
__device__ __align__(16) __nv_bfloat16 g_ql [BH * SEQ * HEAD_DIM];
__device__ __align__(16) __nv_bfloat16 g_kh [BH * SEQ * HEAD_DIM];
__device__ __align__(16) __nv_bfloat16 g_kl [BH * SEQ * HEAD_DIM];
__device__ __align__(16) __nv_bfloat16 g_vh [BH * SEQ * HEAD_DIM];
__device__ __align__(16) __nv_bfloat16 g_vl [BH * SEQ * HEAD_DIM];
__device__ __align__(16) __nv_bfloat16 g_vth[BH * HEAD_DIM * SEQ];
__device__ __align__(16) __nv_bfloat16 g_vtl[BH * HEAD_DIM * SEQ];
__device__ __align__(16) __nv_bfloat16 g_oh [M_TOK * DIMC];
__device__ __align__(16) __nv_bfloat16 g_ol [M_TOK * DIMC];
__device__ __align__(256) float g_attn[ATTN_ELEMS];
__device__ __align__(256) float g_outs[OUT_ELEMS];

// ---------------- helpers ----------------
__device__ __forceinline__ uint32_t smem_u32(const void* p) {
    return (uint32_t)__cvta_generic_to_shared(p);
}
__device__ __forceinline__ void cpasync16(uint32_t dst, const void* src) {
    asm volatile("cp.async.cg.shared.global [%0], [%1], 16;" :: "r"(dst), "l"(src));
}
__device__ __forceinline__ void ldsm_x4(uint32_t* r, uint32_t addr) {
    asm volatile("ldmatrix.sync.aligned.m8n8.x4.shared.b16 {%0,%1,%2,%3}, [%4];"
                 : "=r"(r[0]), "=r"(r[1]), "=r"(r[2]), "=r"(r[3]) : "r"(addr));
}
__device__ __forceinline__ void mma16816(float* c, const uint32_t* a, const uint32_t* b) {
    asm volatile("mma.sync.aligned.m16n8k16.row.col.f32.bf16.bf16.f32 "
                 "{%0,%1,%2,%3}, {%4,%5,%6,%7}, {%8,%9}, {%0,%1,%2,%3};"
                 : "+f"(c[0]), "+f"(c[1]), "+f"(c[2]), "+f"(c[3])
                 : "r"(a[0]), "r"(a[1]), "r"(a[2]), "r"(a[3]), "r"(b[0]), "r"(b[1]));
}
__device__ __forceinline__ void split2(float v, __nv_bfloat16& h, __nv_bfloat16& l) {
    h = __float2bfloat16_rn(v);
    l = __float2bfloat16_rn(v - __bfloat162float(h));
}
__device__ __forceinline__ uint32_t pack_bf2(__nv_bfloat16 a, __nv_bfloat16 b) {
    __nv_bfloat162 t(a, b);
    return *(uint32_t*)&t;
}

// ============================================================================
// R4 mainloop: block 128 x BN of C = A @ B^T, 256 threads, warps 4(m) x 2(n),
// warp tile 32x64 (BN=128) or 32x32 (BN=64).  k32 chunks, 2-stage cp.async.
// ============================================================================
#define SPAD 40

template<int BN>
__device__ __forceinline__ void gemm_tile(
    const __nv_bfloat16* __restrict__ Agh, const __nv_bfloat16* __restrict__ Agl, int lda,
    const __nv_bfloat16* __restrict__ Bgh, const __nv_bfloat16* __restrict__ Bgl, int ldb,
    int K, float (&acc)[2][BN / 16][4])
{
    extern __shared__ char smem_raw[];
    constexpr int NT   = BN / 16;
    constexpr int ASZ  = 128 * SPAD * 2;
    constexpr int BSZ  = BN  * SPAD * 2;
    constexpr int STAGE = 2 * ASZ + 2 * BSZ;

    const int tid  = threadIdx.x;
    const int lane = tid & 31;
    const int warp = tid >> 5;
    const int wm = (warp >> 1) * 32;
    const int wn = (warp & 1) * (BN / 2);

    const int lc = tid & 3;
    const int lr = tid >> 2;

    const uint32_t sbase = smem_u32(smem_raw);

    auto load_stage = [&](int s, int k0) {
        uint32_t base = sbase + s * STAGE;
#pragma unroll
        for (int rr = 0; rr < 2; rr++) {
            int row = lr + rr * 64;
            uint32_t doff = (uint32_t)(row * SPAD + lc * 8) * 2;
            cpasync16(base + doff,       Agh + (size_t)row * lda + k0 + lc * 8);
            cpasync16(base + ASZ + doff, Agl + (size_t)row * lda + k0 + lc * 8);
        }
#pragma unroll
        for (int rr = 0; rr < BN / 64; rr++) {
            int row = lr + rr * 64;
            uint32_t doff = (uint32_t)(row * SPAD + lc * 8) * 2;
            cpasync16(base + 2 * ASZ + doff,       Bgh + (size_t)row * ldb + k0 + lc * 8);
            cpasync16(base + 2 * ASZ + BSZ + doff, Bgl + (size_t)row * ldb + k0 + lc * 8);
        }
    };

    const int a_row = wm + (lane & 15);
    const int a_co  = (lane >> 4) << 3;
    const int g     = lane >> 3;
    const int b_rowbase = wn + (g >> 1) * 8 + (lane & 7);
    const int b_co  = (g & 1) * 8;

    int niter = K >> 5;
    load_stage(0, 0);
    asm volatile("cp.async.commit_group;");

    for (int it = 0; it < niter; it++) {
        int buf = it & 1;
        if (it + 1 < niter) {
            load_stage(buf ^ 1, (it + 1) * 32);
            asm volatile("cp.async.commit_group;");
            asm volatile("cp.async.wait_group 1;");
        } else {
            asm volatile("cp.async.wait_group 0;");
        }
        __syncthreads();

        uint32_t sb = sbase + buf * STAGE;
#pragma unroll
        for (int k16 = 0; k16 < 32; k16 += 16) {
            uint32_t ah[2][4], al[2][4];
#pragma unroll
            for (int mt = 0; mt < 2; mt++) {
                uint32_t addr = sb + (uint32_t)(((a_row + mt * 16) * SPAD + k16 + a_co) * 2);
                ldsm_x4(ah[mt], addr);
                ldsm_x4(al[mt], addr + ASZ);
            }
            uint32_t bhf[NT][2], blf[NT][2];
#pragma unroll
            for (int u = 0; u < NT; u += 2) {
                uint32_t addr = sb + 2 * ASZ +
                    (uint32_t)(((b_rowbase + u * 8) * SPAD + k16 + b_co) * 2);
                uint32_t t[4];
                ldsm_x4(t, addr);
                bhf[u][0] = t[0]; bhf[u][1] = t[1];
                bhf[u + 1][0] = t[2]; bhf[u + 1][1] = t[3];
                ldsm_x4(t, addr + BSZ);
                blf[u][0] = t[0]; blf[u][1] = t[1];
                blf[u + 1][0] = t[2]; blf[u + 1][1] = t[3];
            }
#pragma unroll
            for (int mt = 0; mt < 2; mt++) {
#pragma unroll
                for (int u = 0; u < NT; u++) {
                    mma16816(acc[mt][u], ah[mt], bhf[u]);
                    mma16816(acc[mt][u], ah[mt], blf[u]);
                    mma16816(acc[mt][u], al[mt], bhf[u]);
                }
            }
        }
        __syncthreads();
    }
}

// ============================================================================
// split: fp32 -> (hi, lo) bf16
// ============================================================================
__global__ __launch_bounds__(256)
void split_kernel(const float4* __restrict__ src, __nv_bfloat162* __restrict__ hi,
                  __nv_bfloat162* __restrict__ lo, int n4)
{
    int i = blockIdx.x * blockDim.x + threadIdx.x;
    if (i >= n4) return;
    float4 v = src[i];
    __nv_bfloat16 h0, h1, h2, h3, l0, l1, l2, l3;
    split2(v.x, h0, l0); split2(v.y, h1, l1);
    split2(v.z, h2, l2); split2(v.w, h3, l3);
    hi[2 * i]     = __nv_bfloat162(h0, h1);
    hi[2 * i + 1] = __nv_bfloat162(h2, h3);
    lo[2 * i]     = __nv_bfloat162(l0, l1);
    lo[2 * i + 1] = __nv_bfloat162(l2, l3);
}

// ============================================================================
// K1: QKV GEMM [4096 x 2304] (R4 config).  Epilogue scatters q/k/v hi/lo.
// ============================================================================
__global__ __launch_bounds__(256)
void qkv_mma()
{
    float acc[2][8][4];
#pragma unroll
    for (int a = 0; a < 2; a++)
#pragma unroll
        for (int b = 0; b < 8; b++)
#pragma unroll
            for (int c = 0; c < 4; c++) acc[a][b][c] = 0.f;

    const int bx = blockIdx.x, by = blockIdx.y;
    gemm_tile<128>(g_xh + (size_t)(by * 128) * DIMC, g_xl + (size_t)(by * 128) * DIMC, DIMC,
                   g_wqh + (size_t)(bx * 128) * DIMC, g_wql + (size_t)(bx * 128) * DIMC, DIMC,
                   DIMC, acc);

    const int lane = threadIdx.x & 31, warp = threadIdx.x >> 5;
    const int wm = (warp >> 1) * 32, wn = (warp & 1) * 64;
    const int r = lane >> 2, cc = (lane & 3) * 2;

    const int which = bx / 6;
    __nv_bfloat16 *dh, *dl;
    float scl = 1.f;
    if (which == 0)      { dh = g_qh; dl = g_ql; scl = SCALE_F; }
    else if (which == 1) { dh = g_kh; dl = g_kl; }
    else                 { dh = g_vh; dl = g_vl; }
    const int cbase = bx * 128 - which * DIMC;

#pragma unroll
    for (int mt = 0; mt < 2; mt++) {
#pragma unroll
        for (int nt = 0; nt < 8; nt++) {
            int c = cbase + wn + nt * 8 + cc;
            int h = c >> 6, d = c & 63;
#pragma unroll
            for (int half = 0; half < 2; half++) {
                int m = by * 128 + wm + mt * 16 + r + half * 8;
                int b = m >> 10, qi = m & 1023;
                size_t idx = (((size_t)(b * NUM_HEADS + h) * SEQ) + qi) * HEAD_DIM + d;
                float v0 = acc[mt][nt][half * 2]     * scl;
                float v1 = acc[mt][nt][half * 2 + 1] * scl;
                __nv_bfloat16 h0, h1, l0, l1;
                split2(v0, h0, l0); split2(v1, h1, l1);
                *(__nv_bfloat162*)&dh[idx] = __nv_bfloat162(h0, h1);
                *(__nv_bfloat162*)&dl[idx] = __nv_bfloat162(l0, l1);
            }
        }
    }
}

// ============================================================================
// K2: transpose v -> vt (hi, lo)
// ============================================================================
__global__ __launch_bounds__(256)
void vt_kernel()
{
    __shared__ __nv_bfloat16 tile[32][33];
    const int bh = blockIdx.z, bx = blockIdx.x, by = blockIdx.y;
    const int tx = threadIdx.x, ty = threadIdx.y;
#pragma unroll
    for (int which = 0; which < 2; which++) {
        const __nv_bfloat16* src = (which ? g_vl : g_vh) + (size_t)bh * SEQ * HEAD_DIM;
        __nv_bfloat16* dst = (which ? g_vtl : g_vth) + (size_t)bh * HEAD_DIM * SEQ;
#pragma unroll
        for (int j = 0; j < 4; j++) {
            int s = bx * 32 + ty + j * 8;
            tile[ty + j * 8][tx] = src[(size_t)s * HEAD_DIM + by * 32 + tx];
        }
        __syncthreads();
#pragma unroll
        for (int j = 0; j < 4; j++) {
            int d = by * 32 + ty + j * 8;
            dst[(size_t)d * SEQ + bx * 32 + tx] = tile[tx][ty + j * 8];
        }
        __syncthreads();
    }
}

// ============================================================================
// K3: S = q @ k^T per (b,h) (R4 config).
// ============================================================================
__global__ __launch_bounds__(256)
void s_mma(float* attn_out)
{
    float* attn = attn_out ? attn_out : g_attn;
    float acc[2][8][4];
#pragma unroll
    for (int a = 0; a < 2; a++)
#pragma unroll
        for (int b = 0; b < 8; b++)
#pragma unroll
            for (int c = 0; c < 4; c++) acc[a][b][c] = 0.f;

    const int bh = blockIdx.z, bx = blockIdx.x, by = blockIdx.y;
    const size_t hb = (size_t)bh * SEQ * HEAD_DIM;
    gemm_tile<128>(g_qh + hb + (size_t)(by * 128) * HEAD_DIM,
                   g_ql + hb + (size_t)(by * 128) * HEAD_DIM, HEAD_DIM,
                   g_kh + hb + (size_t)(bx * 128) * HEAD_DIM,
                   g_kl + hb + (size_t)(bx * 128) * HEAD_DIM, HEAD_DIM,
                   HEAD_DIM, acc);

    const int lane = threadIdx.x & 31, warp = threadIdx.x >> 5;
    const int wm = (warp >> 1) * 32, wn = (warp & 1) * 64;
    const int r = lane >> 2, cc = (lane & 3) * 2;
    float* C = attn + (size_t)bh * SEQ * SEQ;

#pragma unroll
    for (int mt = 0; mt < 2; mt++) {
#pragma unroll
        for (int nt = 0; nt < 8; nt++) {
            int n = bx * 128 + wn + nt * 8 + cc;
#pragma unroll
            for (int half = 0; half < 2; half++) {
                int m = by * 128 + wm + mt * 16 + r + half * 8;
                *(float2*)&C[(size_t)m * SEQ + n] =
                    make_float2(acc[mt][nt][half * 2], acc[mt][nt][half * 2 + 1]);
            }
        }
    }
}

// ============================================================================
// K4: row softmax in place (normalized fp32 attn only — no bf16 emission)
// ============================================================================
__global__ __launch_bounds__(256)
void softmax_kernel(float* attn_out)
{
    float* attn = attn_out ? attn_out : g_attn;
    float* p = attn + (size_t)blockIdx.x * SEQ;
    const int tid = threadIdx.x;
    __shared__ float red_max[8];
    __shared__ float red_sum[8];

    float4 v = reinterpret_cast<float4*>(p)[tid];
    float m = fmaxf(fmaxf(v.x, v.y), fmaxf(v.z, v.w));
#pragma unroll
    for (int o = 16; o > 0; o >>= 1) m = fmaxf(m, __shfl_xor_sync(0xFFFFFFFFu, m, o));
    if ((tid & 31) == 0) red_max[tid >> 5] = m;
    __syncthreads();
    if (tid == 0) {
        float t = red_max[0];
#pragma unroll
        for (int i = 1; i < 8; i++) t = fmaxf(t, red_max[i]);
        red_max[0] = t;
    }
    __syncthreads();
    const float rmax = red_max[0];

    v.x = expf(v.x - rmax); v.y = expf(v.y - rmax);
    v.z = expf(v.z - rmax); v.w = expf(v.w - rmax);
    float s = v.x + v.y + v.z + v.w;
#pragma unroll
    for (int o = 16; o > 0; o >>= 1) s += __shfl_xor_sync(0xFFFFFFFFu, s, o);
    if ((tid & 31) == 0) red_sum[tid >> 5] = s;
    __syncthreads();
    if (tid == 0) {
        float t = 0.f;
#pragma unroll
        for (int i = 0; i < 8; i++) t += red_sum[i];
        red_sum[0] = t;
    }
    __syncthreads();
    const float inv = 1.0f / red_sum[0];
    v.x *= inv; v.y *= inv; v.z *= inv; v.w *= inv;
    reinterpret_cast<float4*>(p)[tid] = v;
}

// ============================================================================
// K5: O = P @ vt^T per (b,h).  BM=128, BN=64, 8 warps (32x32 tiles), K=1024.
// A = normalized fp32 attn: LDG -> split hi/lo -> STS (same smem layout as
// the cp.async path).  B = vt hi/lo via cp.async.  Forced 2 CTAs/SM.
// ============================================================================
__global__ __launch_bounds__(256, 2)
void o_mma(const float* attn_in)
{
    const float* attn = attn_in ? attn_in : g_attn;
    constexpr int BM = 128, BN = 64;
    constexpr int APL = BM * SPAD * 2;       // 10240
    constexpr int BPL = BN * SPAD * 2;       // 5120
    constexpr int STAGE = 2 * APL + 2 * BPL; // 30720
    extern __shared__ char smem_raw[];

    const int tid = threadIdx.x, lane = tid & 31, warp = tid >> 5;
    const int bh = blockIdx.y, bx = blockIdx.x;
    const int b = bh / NUM_HEADS, h = bh - b * NUM_HEADS;
    const float* Pg = attn + (size_t)bh * SEQ * SEQ + (size_t)(bx * 128) * SEQ;
    const __nv_bfloat16* Bgh = g_vth + (size_t)bh * HEAD_DIM * SEQ;
    const __nv_bfloat16* Bgl = g_vtl + (size_t)bh * HEAD_DIM * SEQ;
    const uint32_t sb0 = smem_u32(smem_raw);

    float acc[2][4][4];
#pragma unroll
    for (int a = 0; a < 2; a++)
#pragma unroll
        for (int bb = 0; bb < 4; bb++)
#pragma unroll
            for (int c = 0; c < 4; c++) acc[a][bb][c] = 0.f;

    // A: 128 rows x 4 chunks = 512 units / 256 threads = 2 per thread
    uint4 hr[2], lr_[2];
    auto ldgA = [&](int k0) {
#pragma unroll
        for (int u = 0; u < 2; u++) {
            int p = tid + u * 256;
            int row = p >> 2, ch = p & 3;
            const float* s = Pg + (size_t)row * SEQ + k0 + ch * 8;
            float4 a = *(const float4*)s;
            float4 c = *(const float4*)(s + 4);
            __nv_bfloat16 h0,h1,h2,h3,h4,h5,h6,h7, l0,l1,l2,l3,l4,l5,l6,l7;
            split2(a.x,h0,l0); split2(a.y,h1,l1); split2(a.z,h2,l2); split2(a.w,h3,l3);
            split2(c.x,h4,l4); split2(c.y,h5,l5); split2(c.z,h6,l6); split2(c.w,h7,l7);
            hr[u]  = make_uint4(pack_bf2(h0,h1), pack_bf2(h2,h3),
                                pack_bf2(h4,h5), pack_bf2(h6,h7));
            lr_[u] = make_uint4(pack_bf2(l0,l1), pack_bf2(l2,l3),
                                pack_bf2(l4,l5), pack_bf2(l6,l7));
        }
    };
    auto stsA = [&](int buf) {
        char* base = smem_raw + buf * STAGE;
#pragma unroll
        for (int u = 0; u < 2; u++) {
            int p = tid + u * 256;
            int row = p >> 2, ch = p & 3;
            uint32_t off = (uint32_t)(row * SPAD + ch * 8) * 2;
            *(uint4*)(base + off)       = hr[u];
            *(uint4*)(base + APL + off) = lr_[u];
        }
    };
    auto fillB = [&](int buf, int k0) {
        int row = tid >> 2, ch = tid & 3;   // 64 rows x 4 chunks = 256 units
        uint32_t off = (uint32_t)(row * SPAD + ch * 8) * 2;
        uint32_t base = sb0 + (uint32_t)buf * STAGE;
        cpasync16(base + 2 * APL + off,       Bgh + (size_t)row * SEQ + k0 + ch * 8);
        cpasync16(base + 2 * APL + BPL + off, Bgl + (size_t)row * SEQ + k0 + ch * 8);
        asm volatile("cp.async.commit_group;");
    };

    const int wm = (warp >> 1) * 32, wn = (warp & 1) * 32;
    const int a_row = wm + (lane & 15);
    const int a_co  = (lane >> 4) << 3;
    const int g     = lane >> 3;
    const int b_rowbase = wn + (g >> 1) * 8 + (lane & 7);
    const int b_co  = (g & 1) * 8;

    const int niter = SEQ >> 5;     // 32
    ldgA(0); stsA(0);
    fillB(0, 0);
    for (int it = 0; it < niter; it++) {
        if (it + 1 < niter) {
            ldgA((it + 1) * 32);
            fillB((it + 1) & 1, (it + 1) * 32);
            asm volatile("cp.async.wait_group 1;");
        } else {
            asm volatile("cp.async.wait_group 0;");
        }
        __syncthreads();
        const uint32_t sb = sb0 + (uint32_t)(it & 1) * STAGE;
#pragma unroll
        for (int k16 = 0; k16 < 32; k16 += 16) {
            uint32_t ah[2][4], al[2][4];
#pragma unroll
            for (int mt = 0; mt < 2; mt++) {
                uint32_t addr = sb + (uint32_t)(((a_row + mt * 16) * SPAD + k16 + a_co) * 2);
                ldsm_x4(ah[mt], addr);
                ldsm_x4(al[mt], addr + APL);
            }
            uint32_t bhf[4][2], blf[4][2];
#pragma unroll
            for (int u = 0; u < 4; u += 2) {
                uint32_t addr = sb + 2 * APL +
                    (uint32_t)(((b_rowbase + u * 8) * SPAD + k16 + b_co) * 2);
                uint32_t t[4];
                ldsm_x4(t, addr);
                bhf[u][0] = t[0]; bhf[u][1] = t[1];
                bhf[u + 1][0] = t[2]; bhf[u + 1][1] = t[3];
                ldsm_x4(t, addr + BPL);
                blf[u][0] = t[0]; blf[u][1] = t[1];
                blf[u + 1][0] = t[2]; blf[u + 1][1] = t[3];
            }
#pragma unroll
            for (int mt = 0; mt < 2; mt++) {
#pragma unroll
                for (int u = 0; u < 4; u++) {
                    mma16816(acc[mt][u], ah[mt], bhf[u]);
                    mma16816(acc[mt][u], ah[mt], blf[u]);
                    mma16816(acc[mt][u], al[mt], bhf[u]);
                }
            }
        }
        if (it + 1 < niter) stsA((it + 1) & 1);
        __syncthreads();
    }

    // epilogue -> O hi/lo in [B,S,C]
    const int r = lane >> 2, cc = (lane & 3) * 2;
#pragma unroll
    for (int mt = 0; mt < 2; mt++) {
#pragma unroll
        for (int nt = 0; nt < 4; nt++) {
            int d = wn + nt * 8 + cc;
#pragma unroll
            for (int half = 0; half < 2; half++) {
                int mseq = bx * 128 + wm + mt * 16 + r + half * 8;
                size_t idx = ((size_t)b * SEQ + mseq) * DIMC + h * HEAD_DIM + d;
                float v0 = acc[mt][nt][half * 2];
                float v1 = acc[mt][nt][half * 2 + 1];
                __nv_bfloat16 h0, h1, l0, l1;
                split2(v0, h0, l0); split2(v1, h1, l1);
                *(__nv_bfloat162*)&g_oh[idx] = __nv_bfloat162(h0, h1);
                *(__nv_bfloat162*)&g_ol[idx] = __nv_bfloat162(l0, l1);
            }
        }
    }
}

// ============================================================================
// K6: out = O @ w_proj^T + bias (R4 config).
// ============================================================================
__global__ __launch_bounds__(256)
void proj_mma(const float* __restrict__ bias, float* out_ptr)
{
    float* outp = out_ptr ? out_ptr : g_outs;
    float acc[2][8][4];
#pragma unroll
    for (int a = 0; a < 2; a++)
#pragma unroll
        for (int b = 0; b < 8; b++)
#pragma unroll
            for (int c = 0; c < 4; c++) acc[a][b][c] = 0.f;

    const int bx = blockIdx.x, by = blockIdx.y;
    gemm_tile<128>(g_oh + (size_t)(by * 128) * DIMC, g_ol + (size_t)(by * 128) * DIMC, DIMC,
                   g_wph + (size_t)(bx * 128) * DIMC, g_wpl + (size_t)(bx * 128) * DIMC, DIMC,
                   DIMC, acc);

    const int lane = threadIdx.x & 31, warp = threadIdx.x >> 5;
    const int wm = (warp >> 1) * 32, wn = (warp & 1) * 64;
    const int r = lane >> 2, cc = (lane & 3) * 2;

#pragma unroll
    for (int mt = 0; mt < 2; mt++) {
#pragma unroll
        for (int nt = 0; nt < 8; nt++) {
            int n = bx * 128 + wn + nt * 8 + cc;
            float b0 = bias[n], b1 = bias[n + 1];
#pragma unroll
            for (int half = 0; half < 2; half++) {
                int m = by * 128 + wm + mt * 16 + r + half * 8;
                *(float2*)&outp[(size_t)m * DIMC + n] =
                    make_float2(acc[mt][nt][half * 2] + b0, acc[mt][nt][half * 2 + 1] + b1);
            }
        }
    }
}

// ============================================================================
// launch
// ============================================================================
extern "C" void kernel_launch(void* const* d_in, const int* in_sizes, int n_in,
                              void* d_out, int out_size)
{
    const float* x      = (const float*)d_in[0];
    const float* w_qkv  = (const float*)d_in[1];
    const float* w_proj = (const float*)d_in[2];
    const float* b_proj = (const float*)d_in[3];
    (void)in_sizes; (void)n_in;

    float* dof = (float*)d_out;
    float* out_ptr  = nullptr;
    float* attn_ptr = nullptr;
    size_t osz = (size_t)out_size;
    if (osz >= OUT_ELEMS + ATTN_ELEMS) { out_ptr = dof; attn_ptr = dof + OUT_ELEMS; }
    else if (osz == ATTN_ELEMS)        { attn_ptr = dof; }
    else                               { out_ptr = dof; }

    const int SM_BIG = 2 * (2 * 128 * SPAD * 2 + 2 * 128 * SPAD * 2);  // 81920
    const int SM_O   = 2 * (2 * 128 * SPAD * 2 + 2 * 64  * SPAD * 2);  // 61440
    cudaFuncSetAttribute(qkv_mma,  cudaFuncAttributeMaxDynamicSharedMemorySize, SM_BIG);
    cudaFuncSetAttribute(s_mma,    cudaFuncAttributeMaxDynamicSharedMemorySize, SM_BIG);
    cudaFuncSetAttribute(proj_mma, cudaFuncAttributeMaxDynamicSharedMemorySize, SM_BIG);
    cudaFuncSetAttribute(o_mma,    cudaFuncAttributeMaxDynamicSharedMemorySize, SM_O);

    void *p_xh, *p_xl, *p_wqh, *p_wql, *p_wph, *p_wpl;
    cudaGetSymbolAddress(&p_xh, g_xh);   cudaGetSymbolAddress(&p_xl, g_xl);
    cudaGetSymbolAddress(&p_wqh, g_wqh); cudaGetSymbolAddress(&p_wql, g_wql);
    cudaGetSymbolAddress(&p_wph, g_wph); cudaGetSymbolAddress(&p_wpl, g_wpl);

    dim3 blk(256);

    { int n4 = M_TOK * DIMC / 4;
      split_kernel<<<(n4 + 255) / 256, blk>>>((const float4*)x,
          (__nv_bfloat162*)p_xh, (__nv_bfloat162*)p_xl, n4); }
    { int n4 = QKV_N * DIMC / 4;
      split_kernel<<<(n4 + 255) / 256, blk>>>((const float4*)w_qkv,
          (__nv_bfloat162*)p_wqh, (__nv_bfloat162*)p_wql, n4); }
    { int n4 = DIMC * DIMC / 4;
      split_kernel<<<(n4 + 255) / 256, blk>>>((const float4*)w_proj,
          (__nv_bfloat162*)p_wph, (__nv_bfloat162*)p_wpl, n4); }

    qkv_mma<<<dim3(QKV_N / 128, M_TOK / 128), blk, SM_BIG>>>();

    vt_kernel<<<dim3(SEQ / 32, HEAD_DIM / 32, BH), dim3(32, 8)>>>();

    s_mma<<<dim3(SEQ / 128, SEQ / 128, BH), blk, SM_BIG>>>(attn_ptr);

    softmax_kernel<<<dim3(BH * SEQ), blk>>>(attn_ptr);

    o_mma<<<dim3(SEQ / 128, BH), blk, SM_O>>>(attn_ptr);

    proj_mma<<<dim3(DIMC / 128, M_TOK / 128), blk, SM_BIG>>>(b_proj, out_ptr);
}

// round 10
// speedup vs baseline: 1.2828x; 1.0296x over previous
#include <cuda_runtime.h>
#include <cuda_bf16.h>
#include <cstdint>

// ============================================================================
// Attention_84129819394524 — bf16-split mma.sync (R4 config, 483us baseline)
// Single delta vs R4: MMA issue reordered TERM-MAJOR (all hh, all hl, all lh)
// to break the per-accumulator RAW chain (was 3 dependent MMAs back-to-back).
// Bit-identical arithmetic; targets the tensor-pipe dependency stall.
// ============================================================================

#define NUM_HEADS 12
#define HEAD_DIM  64
#define DIMC      768
#define BATCH     4
#define SEQ       1024
#define SCALE_F   0.125f

#define M_TOK   (BATCH * SEQ)          // 4096
#define QKV_N   (3 * DIMC)             // 2304
#define BH      (BATCH * NUM_HEADS)    // 48

#define OUT_ELEMS  ((size_t)M_TOK * DIMC)
#define ATTN_ELEMS ((size_t)BH * SEQ * SEQ)

// ---------------- device scratch (allocation-free) ----------------
__device__ __align__(16) __nv_bfloat16 g_xh [M_TOK * DIMC];
__device__ __align__(16) __nv_bfloat16 g_xl [M_TOK * DIMC];
__device__ __align__(16) __nv_bfloat16 g_wqh[QKV_N * DIMC];
__device__ __align__(16) __nv_bfloat16 g_wql[QKV_N * DIMC];
__device__ __align__(16) __nv_bfloat16 g_wph[DIMC * DIMC];
__device__ __align__(16) __nv_bfloat16 g_wpl[DIMC * DIMC];
__device__ __align__(16) __nv_bfloat16 g_qh [BH * SEQ * HEAD_DIM];
__device__ __align__(16) __nv_bfloat16 g_ql [BH * SEQ * HEAD_DIM];
__device__ __align__(16) __nv_bfloat16 g_kh [BH * SEQ * HEAD_DIM];
__device__ __align__(16) __nv_bfloat16 g_kl [BH * SEQ * HEAD_DIM];
__device__ __align__(16) __nv_bfloat16 g_vh [BH * SEQ * HEAD_DIM];
__device__ __align__(16) __nv_bfloat16 g_vl [BH * SEQ * HEAD_DIM];
__device__ __align__(16) __nv_bfloat16 g_vth[BH * HEAD_DIM * SEQ];
__device__ __align__(16) __nv_bfloat16 g_vtl[BH * HEAD_DIM * SEQ];
__device__ __align__(16) __nv_bfloat16 g_ph [BH * SEQ * SEQ];
__device__ __align__(16) __nv_bfloat16 g_pl [BH * SEQ * SEQ];
__device__ __align__(16) __nv_bfloat16 g_oh [M_TOK * DIMC];
__device__ __align__(16) __nv_bfloat16 g_ol [M_TOK * DIMC];
__device__ __align__(256) float g_attn[ATTN_ELEMS];
__device__ __align__(256) float g_outs[OUT_ELEMS];

// ---------------- helpers ----------------
__device__ __forceinline__ uint32_t smem_u32(const void* p) {
    return (uint32_t)__cvta_generic_to_shared(p);
}
__device__ __forceinline__ void cpasync16(uint32_t dst, const void* src) {
    asm volatile("cp.async.cg.shared.global [%0], [%1], 16;" :: "r"(dst), "l"(src));
}
__device__ __forceinline__ void ldsm_x4(uint32_t* r, uint32_t addr) {
    asm volatile("ldmatrix.sync.aligned.m8n8.x4.shared.b16 {%0,%1,%2,%3}, [%4];"
                 : "=r"(r[0]), "=r"(r[1]), "=r"(r[2]), "=r"(r[3]) : "r"(addr));
}
__device__ __forceinline__ void mma16816(float* c, const uint32_t* a, const uint32_t* b) {
    asm volatile("mma.sync.aligned.m16n8k16.row.col.f32.bf16.bf16.f32 "
                 "{%0,%1,%2,%3}, {%4,%5,%6,%7}, {%8,%9}, {%0,%1,%2,%3};"
                 : "+f"(c[0]), "+f"(c[1]), "+f"(c[2]), "+f"(c[3])
                 : "r"(a[0]), "r"(a[1]), "r"(a[2]), "r"(a[3]), "r"(b[0]), "r"(b[1]));
}
__device__ __forceinline__ void split2(float v, __nv_bfloat16& h, __nv_bfloat16& l) {
    h = __float2bfloat16_rn(v);
    l = __float2bfloat16_rn(v - __bfloat162float(h));
}

// ============================================================================
// Mainloop: block 128 x BN of C = A @ B^T, 256 threads, warps 4(m) x 2(n),
// warp tile 32x64 (BN=128) / 32x32 (BN=64).  k32 chunks, 2-stage cp.async.
// MMA issue is TERM-MAJOR: same-acc reuse distance = 2*NT instructions.
// ============================================================================
#define SPAD 40

template<int BN>
__device__ __forceinline__ void gemm_tile(
    const __nv_bfloat16* __restrict__ Agh, const __nv_bfloat16* __restrict__ Agl, int lda,
    const __nv_bfloat16* __restrict__ Bgh, const __nv_bfloat16* __restrict__ Bgl, int ldb,
    int K, float (&acc)[2][BN / 16][4])
{
    extern __shared__ char smem_raw[];
    constexpr int NT   = BN / 16;
    constexpr int ASZ  = 128 * SPAD * 2;
    constexpr int BSZ  = BN  * SPAD * 2;
    constexpr int STAGE = 2 * ASZ + 2 * BSZ;

    const int tid  = threadIdx.x;
    const int lane = tid & 31;
    const int warp = tid >> 5;
    const int wm = (warp >> 1) * 32;
    const int wn = (warp & 1) * (BN / 2);

    const int lc = tid & 3;
    const int lr = tid >> 2;

    const uint32_t sbase = smem_u32(smem_raw);

    auto load_stage = [&](int s, int k0) {
        uint32_t base = sbase + s * STAGE;
#pragma unroll
        for (int rr = 0; rr < 2; rr++) {
            int row = lr + rr * 64;
            uint32_t doff = (uint32_t)(row * SPAD + lc * 8) * 2;
            cpasync16(base + doff,       Agh + (size_t)row * lda + k0 + lc * 8);
            cpasync16(base + ASZ + doff, Agl + (size_t)row * lda + k0 + lc * 8);
        }
#pragma unroll
        for (int rr = 0; rr < BN / 64; rr++) {
            int row = lr + rr * 64;
            uint32_t doff = (uint32_t)(row * SPAD + lc * 8) * 2;
            cpasync16(base + 2 * ASZ + doff,       Bgh + (size_t)row * ldb + k0 + lc * 8);
            cpasync16(base + 2 * ASZ + BSZ + doff, Bgl + (size_t)row * ldb + k0 + lc * 8);
        }
    };

    const int a_row = wm + (lane & 15);
    const int a_co  = (lane >> 4) << 3;
    const int g     = lane >> 3;
    const int b_rowbase = wn + (g >> 1) * 8 + (lane & 7);
    const int b_co  = (g & 1) * 8;

    int niter = K >> 5;
    load_stage(0, 0);
    asm volatile("cp.async.commit_group;");

    for (int it = 0; it < niter; it++) {
        int buf = it & 1;
        if (it + 1 < niter) {
            load_stage(buf ^ 1, (it + 1) * 32);
            asm volatile("cp.async.commit_group;");
            asm volatile("cp.async.wait_group 1;");
        } else {
            asm volatile("cp.async.wait_group 0;");
        }
        __syncthreads();

        uint32_t sb = sbase + buf * STAGE;
#pragma unroll
        for (int k16 = 0; k16 < 32; k16 += 16) {
            uint32_t ah[2][4], al[2][4];
#pragma unroll
            for (int mt = 0; mt < 2; mt++) {
                uint32_t addr = sb + (uint32_t)(((a_row + mt * 16) * SPAD + k16 + a_co) * 2);
                ldsm_x4(ah[mt], addr);
                ldsm_x4(al[mt], addr + ASZ);
            }
            uint32_t bhf[NT][2], blf[NT][2];
#pragma unroll
            for (int u = 0; u < NT; u += 2) {
                uint32_t addr = sb + 2 * ASZ +
                    (uint32_t)(((b_rowbase + u * 8) * SPAD + k16 + b_co) * 2);
                uint32_t t[4];
                ldsm_x4(t, addr);
                bhf[u][0] = t[0]; bhf[u][1] = t[1];
                bhf[u + 1][0] = t[2]; bhf[u + 1][1] = t[3];
                ldsm_x4(t, addr + BSZ);
                blf[u][0] = t[0]; blf[u][1] = t[1];
                blf[u + 1][0] = t[2]; blf[u + 1][1] = t[3];
            }
            // TERM-MAJOR issue: distance between writes to the same acc
            // is 2*NT MMAs (>= pipeline latency), vs 1 in the old order.
            // Per-acc addition order (hh, hl, lh) unchanged -> bit-identical.
#pragma unroll
            for (int mt = 0; mt < 2; mt++)
#pragma unroll
                for (int u = 0; u < NT; u++)
                    mma16816(acc[mt][u], ah[mt], bhf[u]);
#pragma unroll
            for (int mt = 0; mt < 2; mt++)
#pragma unroll
                for (int u = 0; u < NT; u++)
                    mma16816(acc[mt][u], ah[mt], blf[u]);
#pragma unroll
            for (int mt = 0; mt < 2; mt++)
#pragma unroll
                for (int u = 0; u < NT; u++)
                    mma16816(acc[mt][u], al[mt], bhf[u]);
        }
        __syncthreads();
    }
}

// ============================================================================
// split: fp32 -> (hi, lo) bf16
// ============================================================================
__global__ __launch_bounds__(256)
void split_kernel(const float4* __restrict__ src, __nv_bfloat162* __restrict__ hi,
                  __nv_bfloat162* __restrict__ lo, int n4)
{
    int i = blockIdx.x * blockDim.x + threadIdx.x;
    if (i >= n4) return;
    float4 v = src[i];
    __nv_bfloat16 h0, h1, h2, h3, l0, l1, l2, l3;
    split2(v.x, h0, l0); split2(v.y, h1, l1);
    split2(v.z, h2, l2); split2(v.w, h3, l3);
    hi[2 * i]     = __nv_bfloat162(h0, h1);
    hi[2 * i + 1] = __nv_bfloat162(h2, h3);
    lo[2 * i]     = __nv_bfloat162(l0, l1);
    lo[2 * i + 1] = __nv_bfloat162(l2, l3);
}

// ============================================================================
// K1: QKV GEMM [4096 x 2304].  Epilogue scatters q/k/v hi/lo.
// ============================================================================
__global__ __launch_bounds__(256)
void qkv_mma()
{
    float acc[2][8][4];
#pragma unroll
    for (int a = 0; a < 2; a++)
#pragma unroll
        for (int b = 0; b < 8; b++)
#pragma unroll
            for (int c = 0; c < 4; c++) acc[a][b][c] = 0.f;

    const int bx = blockIdx.x, by = blockIdx.y;
    gemm_tile<128>(g_xh + (size_t)(by * 128) * DIMC, g_xl + (size_t)(by * 128) * DIMC, DIMC,
                   g_wqh + (size_t)(bx * 128) * DIMC, g_wql + (size_t)(bx * 128) * DIMC, DIMC,
                   DIMC, acc);

    const int lane = threadIdx.x & 31, warp = threadIdx.x >> 5;
    const int wm = (warp >> 1) * 32, wn = (warp & 1) * 64;
    const int r = lane >> 2, cc = (lane & 3) * 2;

    const int which = bx / 6;           // 0:q 1:k 2:v
    __nv_bfloat16 *dh, *dl;
    float scl = 1.f;
    if (which == 0)      { dh = g_qh; dl = g_ql; scl = SCALE_F; }
    else if (which == 1) { dh = g_kh; dl = g_kl; }
    else                 { dh = g_vh; dl = g_vl; }
    const int cbase = bx * 128 - which * DIMC;

#pragma unroll
    for (int mt = 0; mt < 2; mt++) {
#pragma unroll
        for (int nt = 0; nt < 8; nt++) {
            int c = cbase + wn + nt * 8 + cc;
            int h = c >> 6, d = c & 63;
#pragma unroll
            for (int half = 0; half < 2; half++) {
                int m = by * 128 + wm + mt * 16 + r + half * 8;
                int b = m >> 10, qi = m & 1023;
                size_t idx = (((size_t)(b * NUM_HEADS + h) * SEQ) + qi) * HEAD_DIM + d;
                float v0 = acc[mt][nt][half * 2]     * scl;
                float v1 = acc[mt][nt][half * 2 + 1] * scl;
                __nv_bfloat16 h0, h1, l0, l1;
                split2(v0, h0, l0); split2(v1, h1, l1);
                *(__nv_bfloat162*)&dh[idx] = __nv_bfloat162(h0, h1);
                *(__nv_bfloat162*)&dl[idx] = __nv_bfloat162(l0, l1);
            }
        }
    }
}

// ============================================================================
// K2: transpose v [bh][seq][64] -> vt [bh][64][seq]  (hi and lo)
// ============================================================================
__global__ __launch_bounds__(256)
void vt_kernel()
{
    __shared__ __nv_bfloat16 tile[32][33];
    const int bh = blockIdx.z, bx = blockIdx.x, by = blockIdx.y;
    const int tx = threadIdx.x, ty = threadIdx.y;
#pragma unroll
    for (int which = 0; which < 2; which++) {
        const __nv_bfloat16* src = (which ? g_vl : g_vh) + (size_t)bh * SEQ * HEAD_DIM;
        __nv_bfloat16* dst = (which ? g_vtl : g_vth) + (size_t)bh * HEAD_DIM * SEQ;
#pragma unroll
        for (int j = 0; j < 4; j++) {
            int s = bx * 32 + ty + j * 8;
            tile[ty + j * 8][tx] = src[(size_t)s * HEAD_DIM + by * 32 + tx];
        }
        __syncthreads();
#pragma unroll
        for (int j = 0; j < 4; j++) {
            int d = by * 32 + ty + j * 8;
            dst[(size_t)d * SEQ + bx * 32 + tx] = tile[tx][ty + j * 8];
        }
        __syncthreads();
    }
}

// ============================================================================
// K3: S = q @ k^T per (b,h).  fp32 logits -> attn buffer.
// ============================================================================
__global__ __launch_bounds__(256)
void s_mma(float* attn_out)
{
    float* attn = attn_out ? attn_out : g_attn;
    float acc[2][8][4];
#pragma unroll
    for (int a = 0; a < 2; a++)
#pragma unroll
        for (int b = 0; b < 8; b++)
#pragma unroll
            for (int c = 0; c < 4; c++) acc[a][b][c] = 0.f;

    const int bh = blockIdx.z, bx = blockIdx.x, by = blockIdx.y;
    const size_t hb = (size_t)bh * SEQ * HEAD_DIM;
    gemm_tile<128>(g_qh + hb + (size_t)(by * 128) * HEAD_DIM,
                   g_ql + hb + (size_t)(by * 128) * HEAD_DIM, HEAD_DIM,
                   g_kh + hb + (size_t)(bx * 128) * HEAD_DIM,
                   g_kl + hb + (size_t)(bx * 128) * HEAD_DIM, HEAD_DIM,
                   HEAD_DIM, acc);

    const int lane = threadIdx.x & 31, warp = threadIdx.x >> 5;
    const int wm = (warp >> 1) * 32, wn = (warp & 1) * 64;
    const int r = lane >> 2, cc = (lane & 3) * 2;
    float* C = attn + (size_t)bh * SEQ * SEQ;

#pragma unroll
    for (int mt = 0; mt < 2; mt++) {
#pragma unroll
        for (int nt = 0; nt < 8; nt++) {
            int n = bx * 128 + wn + nt * 8 + cc;
#pragma unroll
            for (int half = 0; half < 2; half++) {
                int m = by * 128 + wm + mt * 16 + r + half * 8;
                *(float2*)&C[(size_t)m * SEQ + n] =
                    make_float2(acc[mt][nt][half * 2], acc[mt][nt][half * 2 + 1]);
            }
        }
    }
}

// ============================================================================
// K4: row softmax in place + emit P hi/lo bf16
// ============================================================================
__global__ __launch_bounds__(256)
void softmax_kernel(float* attn_out)
{
    float* attn = attn_out ? attn_out : g_attn;
    float* p = attn + (size_t)blockIdx.x * SEQ;
    const size_t pbase = (size_t)blockIdx.x * SEQ;
    const int tid = threadIdx.x;
    __shared__ float red_max[8];
    __shared__ float red_sum[8];

    float4 v = reinterpret_cast<float4*>(p)[tid];
    float m = fmaxf(fmaxf(v.x, v.y), fmaxf(v.z, v.w));
#pragma unroll
    for (int o = 16; o > 0; o >>= 1) m = fmaxf(m, __shfl_xor_sync(0xFFFFFFFFu, m, o));
    if ((tid & 31) == 0) red_max[tid >> 5] = m;
    __syncthreads();
    if (tid == 0) {
        float t = red_max[0];
#pragma unroll
        for (int i = 1; i < 8; i++) t = fmaxf(t, red_max[i]);
        red_max[0] = t;
    }
    __syncthreads();
    const float rmax = red_max[0];

    v.x = expf(v.x - rmax); v.y = expf(v.y - rmax);
    v.z = expf(v.z - rmax); v.w = expf(v.w - rmax);
    float s = v.x + v.y + v.z + v.w;
#pragma unroll
    for (int o = 16; o > 0; o >>= 1) s += __shfl_xor_sync(0xFFFFFFFFu, s, o);
    if ((tid & 31) == 0) red_sum[tid >> 5] = s;
    __syncthreads();
    if (tid == 0) {
        float t = 0.f;
#pragma unroll
        for (int i = 0; i < 8; i++) t += red_sum[i];
        red_sum[0] = t;
    }
    __syncthreads();
    const float inv = 1.0f / red_sum[0];
    v.x *= inv; v.y *= inv; v.z *= inv; v.w *= inv;
    reinterpret_cast<float4*>(p)[tid] = v;

    __nv_bfloat16 h0, h1, h2, h3, l0, l1, l2, l3;
    split2(v.x, h0, l0); split2(v.y, h1, l1);
    split2(v.z, h2, l2); split2(v.w, h3, l3);
    size_t idx = pbase + tid * 4;
    *(__nv_bfloat162*)&g_ph[idx]     = __nv_bfloat162(h0, h1);
    *(__nv_bfloat162*)&g_ph[idx + 2] = __nv_bfloat162(h2, h3);
    *(__nv_bfloat162*)&g_pl[idx]     = __nv_bfloat162(l0, l1);
    *(__nv_bfloat162*)&g_pl[idx + 2] = __nv_bfloat162(l2, l3);
}

// ============================================================================
// K5: O = P @ vt^T per (b,h).  128x64, K=1024.  -> O hi/lo in [B,S,C]
// ============================================================================
__global__ __launch_bounds__(256)
void o_mma()
{
    float acc[2][4][4];
#pragma unroll
    for (int a = 0; a < 2; a++)
#pragma unroll
        for (int b = 0; b < 4; b++)
#pragma unroll
            for (int c = 0; c < 4; c++) acc[a][b][c] = 0.f;

    const int bh = blockIdx.y, bx = blockIdx.x;
    const int b = bh / NUM_HEADS, h = bh - b * NUM_HEADS;
    gemm_tile<64>(g_ph + (size_t)bh * SEQ * SEQ + (size_t)(bx * 128) * SEQ,
                  g_pl + (size_t)bh * SEQ * SEQ + (size_t)(bx * 128) * SEQ, SEQ,
                  g_vth + (size_t)bh * HEAD_DIM * SEQ,
                  g_vtl + (size_t)bh * HEAD_DIM * SEQ, SEQ,
                  SEQ, acc);

    const int lane = threadIdx.x & 31, warp = threadIdx.x >> 5;
    const int wm = (warp >> 1) * 32, wn = (warp & 1) * 32;
    const int r = lane >> 2, cc = (lane & 3) * 2;

#pragma unroll
    for (int mt = 0; mt < 2; mt++) {
#pragma unroll
        for (int nt = 0; nt < 4; nt++) {
            int d = wn + nt * 8 + cc;
#pragma unroll
            for (int half = 0; half < 2; half++) {
                int mseq = bx * 128 + wm + mt * 16 + r + half * 8;
                size_t idx = ((size_t)b * SEQ + mseq) * DIMC + h * HEAD_DIM + d;
                float v0 = acc[mt][nt][half * 2];
                float v1 = acc[mt][nt][half * 2 + 1];
                __nv_bfloat16 h0, h1, l0, l1;
                split2(v0, h0, l0); split2(v1, h1, l1);
                *(__nv_bfloat162*)&g_oh[idx] = __nv_bfloat162(h0, h1);
                *(__nv_bfloat162*)&g_ol[idx] = __nv_bfloat162(l0, l1);
            }
        }
    }
}

// ============================================================================
// K6: out = O @ w_proj^T + bias.  [4096 x 768], K=768, fp32 out.
// ============================================================================
__global__ __launch_bounds__(256)
void proj_mma(const float* __restrict__ bias, float* out_ptr)
{
    float* outp = out_ptr ? out_ptr : g_outs;
    float acc[2][8][4];
#pragma unroll
    for (int a = 0; a < 2; a++)
#pragma unroll
        for (int b = 0; b < 8; b++)
#pragma unroll
            for (int c = 0; c < 4; c++) acc[a][b][c] = 0.f;

    const int bx = blockIdx.x, by = blockIdx.y;
    gemm_tile<128>(g_oh + (size_t)(by * 128) * DIMC, g_ol + (size_t)(by * 128) * DIMC, DIMC,
                   g_wph + (size_t)(bx * 128) * DIMC, g_wpl + (size_t)(bx * 128) * DIMC, DIMC,
                   DIMC, acc);

    const int lane = threadIdx.x & 31, warp = threadIdx.x >> 5;
    const int wm = (warp >> 1) * 32, wn = (warp & 1) * 64;
    const int r = lane >> 2, cc = (lane & 3) * 2;

#pragma unroll
    for (int mt = 0; mt < 2; mt++) {
#pragma unroll
        for (int nt = 0; nt < 8; nt++) {
            int n = bx * 128 + wn + nt * 8 + cc;
            float b0 = bias[n], b1 = bias[n + 1];
#pragma unroll
            for (int half = 0; half < 2; half++) {
                int m = by * 128 + wm + mt * 16 + r + half * 8;
                *(float2*)&outp[(size_t)m * DIMC + n] =
                    make_float2(acc[mt][nt][half * 2] + b0, acc[mt][nt][half * 2 + 1] + b1);
            }
        }
    }
}

// ============================================================================
// launch
// ============================================================================
extern "C" void kernel_launch(void* const* d_in, const int* in_sizes, int n_in,
                              void* d_out, int out_size)
{
    const float* x      = (const float*)d_in[0];
    const float* w_qkv  = (const float*)d_in[1];
    const float* w_proj = (const float*)d_in[2];
    const float* b_proj = (const float*)d_in[3];
    (void)in_sizes; (void)n_in;

    float* dof = (float*)d_out;
    float* out_ptr  = nullptr;
    float* attn_ptr = nullptr;
    size_t osz = (size_t)out_size;
    if (osz >= OUT_ELEMS + ATTN_ELEMS) { out_ptr = dof; attn_ptr = dof + OUT_ELEMS; }
    else if (osz == ATTN_ELEMS)        { attn_ptr = dof; }
    else                               { out_ptr = dof; }

    const int SM_BIG = 2 * (2 * 128 * SPAD * 2 + 2 * 128 * SPAD * 2);  // 81920
    const int SM_O   = 2 * (2 * 128 * SPAD * 2 + 2 * 64  * SPAD * 2);  // 61440
    cudaFuncSetAttribute(qkv_mma,  cudaFuncAttributeMaxDynamicSharedMemorySize, SM_BIG);
    cudaFuncSetAttribute(s_mma,    cudaFuncAttributeMaxDynamicSharedMemorySize, SM_BIG);
    cudaFuncSetAttribute(proj_mma, cudaFuncAttributeMaxDynamicSharedMemorySize, SM_BIG);
    cudaFuncSetAttribute(o_mma,    cudaFuncAttributeMaxDynamicSharedMemorySize, SM_O);

    void *p_xh, *p_xl, *p_wqh, *p_wql, *p_wph, *p_wpl;
    cudaGetSymbolAddress(&p_xh, g_xh);   cudaGetSymbolAddress(&p_xl, g_xl);
    cudaGetSymbolAddress(&p_wqh, g_wqh); cudaGetSymbolAddress(&p_wql, g_wql);
    cudaGetSymbolAddress(&p_wph, g_wph); cudaGetSymbolAddress(&p_wpl, g_wpl);

    dim3 blk(256);

    { int n4 = M_TOK * DIMC / 4;
      split_kernel<<<(n4 + 255) / 256, blk>>>((const float4*)x,
          (__nv_bfloat162*)p_xh, (__nv_bfloat162*)p_xl, n4); }
    { int n4 = QKV_N * DIMC / 4;
      split_kernel<<<(n4 + 255) / 256, blk>>>((const float4*)w_qkv,
          (__nv_bfloat162*)p_wqh, (__nv_bfloat162*)p_wql, n4); }
    { int n4 = DIMC * DIMC / 4;
      split_kernel<<<(n4 + 255) / 256, blk>>>((const float4*)w_proj,
          (__nv_bfloat162*)p_wph, (__nv_bfloat162*)p_wpl, n4); }

    qkv_mma<<<dim3(QKV_N / 128, M_TOK / 128), blk, SM_BIG>>>();

    vt_kernel<<<dim3(SEQ / 32, HEAD_DIM / 32, BH), dim3(32, 8)>>>();

    s_mma<<<dim3(SEQ / 128, SEQ / 128, BH), blk, SM_BIG>>>(attn_ptr);

    softmax_kernel<<<dim3(BH * SEQ), blk>>>(attn_ptr);

    o_mma<<<dim3(SEQ / 128, BH), blk, SM_O>>>();

    proj_mma<<<dim3(DIMC / 128, M_TOK / 128), blk, SM_BIG>>>(b_proj, out_ptr);
}